// round 8
// baseline (speedup 1.0000x reference)
#include <cuda_runtime.h>
#include <cuda_fp16.h>
#include <math.h>
#include <stdint.h>

// Problem constants
#define Bsz   512
#define Nn    32
#define Ll    50
#define Hh    256
#define Vv    100000

// ---------------- scratch ----------------
__device__ __align__(256) __half g_hh[Bsz * Nn * Hh];            // node states
__device__ __align__(256) __half g_ah[Bsz * Nn * 2 * Hh];        // GRU input a
__device__ __align__(256) __half g_tcat[Bsz * Nn * 2 * Hh];      // [tin|tout] (half)
__device__ __align__(256) __half g_hseqs[Bsz * Ll * Hh];
__device__ __align__(256) __half g_htail[Bsz * Hh];
__device__ __align__(256) __half g_semb[Bsz * Hh];
__device__ __align__(256) __half g_wcat[512 * Hh];               // [W_in^T ; W_out^T], [N][K]
__device__ __align__(256) __half g_wih[3 * Hh * 2 * Hh];         // [768][512]
__device__ __align__(256) __half g_whh[3 * Hh * Hh];             // [768][256]
__device__ __align__(256) __half g_wf1[Hh * Hh];
__device__ __align__(256) __half g_wf2[Hh * Hh];
__device__ __align__(256) __half g_embh[Vv * Hh];                // emb[1:] in half
// f32 intermediates
__device__ __align__(256) float g_gi[Bsz * Nn * 3 * Hh];
__device__ __align__(256) float g_gh[Bsz * Nn * 3 * Hh];
__device__ __align__(256) float g_q1[Bsz * Hh];
__device__ __align__(256) float g_q2[Bsz * Ll * Hh];
__device__ __align__(256) float g_alpha[Bsz * Ll];
__device__ __align__(256) float g_bcat[2 * Hh];

__device__ __forceinline__ void cpa16(void* dst, const void* src, bool pred) {
    uint32_t d = (uint32_t)__cvta_generic_to_shared(dst);
    int sz = pred ? 16 : 0;
    asm volatile("cp.async.cg.shared.global [%0], [%1], 16, %2;\n"
                 :: "r"(d), "l"(src), "r"(sz));
}
__device__ __forceinline__ void cpa_commit() {
    asm volatile("cp.async.commit_group;\n");
}
__device__ __forceinline__ uint32_t s2u(const void* p) {
    return (uint32_t)__cvta_generic_to_shared(p);
}

// ---------------- weight transpose + halve: src f32 [R][C] -> dst half [C][R] ----------------
__global__ void transpose_h(const float* __restrict__ src, __half* __restrict__ dst,
                            int R, int C) {
    __shared__ float t[32][33];
    int bx = blockIdx.x * 32, by = blockIdx.y * 32;
#pragma unroll
    for (int i = 0; i < 4; i++) {
        int r = by + threadIdx.y + i * 8, c = bx + threadIdx.x;
        if (r < R && c < C) t[threadIdx.y + i * 8][threadIdx.x] = src[(size_t)r * C + c];
    }
    __syncthreads();
#pragma unroll
    for (int i = 0; i < 4; i++) {
        int c = bx + threadIdx.y + i * 8, r = by + threadIdx.x;
        if (c < C && r < R)
            dst[(size_t)c * R + r] = __float2half_rn(t[threadIdx.x][threadIdx.y + i * 8]);
    }
}

// ---------------- emb[1:] -> half ----------------
__global__ void embconv_kernel(const float* __restrict__ emb) {
    size_t i = ((size_t)blockIdx.x * blockDim.x + threadIdx.x) * 4;
    if (i < (size_t)Vv * Hh) {
        float4 v = *(const float4*)(emb + Hh + i);
        __half2* d = (__half2*)(g_embh + i);
        d[0] = __floats2half2_rn(v.x, v.y);
        d[1] = __floats2half2_rn(v.z, v.w);
    }
}

__global__ void bcat_kernel(const float* __restrict__ b_in, const float* __restrict__ b_out) {
    int i = threadIdx.x + blockIdx.x * blockDim.x;
    if (i < 2 * Hh) g_bcat[i] = (i < Hh) ? b_in[i] : b_out[i - Hh];
}

// ---------------- embedding gather -> half ----------------
__global__ void embed_kernel(const float* __restrict__ emb, const int* __restrict__ items) {
    int bn = blockIdx.x;
    int t = threadIdx.x;
    int item = items[bn];
    g_hh[(size_t)bn * Hh + t] = __float2half_rn(emb[(size_t)item * Hh + t]);
}

// ---------------- fp16 tensor-core GEMM (256x128 tile, ldmatrix) ----------------
// C[M,N] = A[M,K] @ B^T (+bias). A:[M][K] half. B:[N][K] half. OutT = float or __half.
// 256 threads, 8 warps as 4x2 -> 64x64 warp tiles. 3-stage cp.async.
// Requires M%256==0, K%32==0. N guarded.
#define LDAh 40                          // halves per smem row (80B), conflict-free
#define ASTG (256 * LDAh)                // 10240 halves
#define BSTG (128 * LDAh)                // 5120 halves
#define STGH (ASTG + BSTG)               // 15360 halves
#define GSM_BYTES (3 * STGH * 2)         // 92160 B
template <typename OutT>
__global__ void __launch_bounds__(256, 1) hgemm(
    const __half* __restrict__ A, const __half* __restrict__ B,
    const float* __restrict__ bias, OutT* __restrict__ C,
    int M, int N, int K)
{
    extern __shared__ __half sm[];
    const int tid = threadIdx.x, wid = tid >> 5, lane = tid & 31;
    const int bm = blockIdx.y * 256;
    const int bn = blockIdx.x * 128;
    const int warpM = wid & 3;           // 4 x 64 rows
    const int warpN = wid >> 2;          // 2 x 64 cols
    const int gr = lane >> 2, kq = lane & 3;
    const int lr7 = lane & 7, lb8 = (lane >> 3) & 1, lb16 = (lane >> 4) & 1;
    const int T = K >> 5;

    float c[4][8][4];
#pragma unroll
    for (int i = 0; i < 4; i++)
#pragma unroll
        for (int j = 0; j < 8; j++)
#pragma unroll
            for (int r = 0; r < 4; r++) c[i][j][r] = 0.f;

    auto load_stage = [&](int kt, int s) {
        __half* stg = sm + s * STGH;
#pragma unroll
        for (int i = 0; i < 4; i++) {            // A: 1024 16B chunks
            int ci = tid + i * 256;
            int row = ci >> 2, q = ci & 3;
            cpa16(stg + row * LDAh + q * 8,
                  A + (size_t)(bm + row) * K + kt * 32 + q * 8, true);
        }
#pragma unroll
        for (int i = 0; i < 2; i++) {            // B: 512 16B chunks
            int ci = tid + i * 256;
            int row = ci >> 2, q = ci & 3;
            cpa16(stg + ASTG + row * LDAh + q * 8,
                  B + (size_t)(bn + row) * K + kt * 32 + q * 8, (bn + row) < N);
        }
        cpa_commit();
    };

    load_stage(0, 0);
    load_stage(1, 1);

    for (int it = 0; it < T; it++) {
        if (it + 2 < T) load_stage(it + 2, (it + 2) % 3);
        if (it + 2 < T)      asm volatile("cp.async.wait_group 2;\n" ::: "memory");
        else if (it + 1 < T) asm volatile("cp.async.wait_group 1;\n" ::: "memory");
        else                 asm volatile("cp.async.wait_group 0;\n" ::: "memory");
        __syncthreads();

        const __half* as = sm + (it % 3) * STGH;
        const uint32_t aB = s2u(as);
        const uint32_t bB = aB + ASTG * 2;
#pragma unroll
        for (int ks = 0; ks < 2; ks++) {
            const int kb = ks * 16;
            uint32_t bf[8][2];
#pragma unroll
            for (int ntp = 0; ntp < 4; ntp++) {
                uint32_t addr = bB + (uint32_t)(
                    (warpN * 64 + ntp * 16 + lr7 + lb16 * 8) * LDAh + kb + lb8 * 8) * 2;
                asm volatile("ldmatrix.sync.aligned.m8n8.x4.shared.b16 {%0,%1,%2,%3}, [%4];"
                             : "=r"(bf[2 * ntp][0]), "=r"(bf[2 * ntp][1]),
                               "=r"(bf[2 * ntp + 1][0]), "=r"(bf[2 * ntp + 1][1])
                             : "r"(addr));
            }
#pragma unroll
            for (int mt = 0; mt < 4; mt++) {
                uint32_t af[4];
                uint32_t addr = aB + (uint32_t)(
                    (warpM * 64 + mt * 16 + lr7 + lb8 * 8) * LDAh + kb + lb16 * 8) * 2;
                asm volatile("ldmatrix.sync.aligned.m8n8.x4.shared.b16 {%0,%1,%2,%3}, [%4];"
                             : "=r"(af[0]), "=r"(af[1]), "=r"(af[2]), "=r"(af[3])
                             : "r"(addr));
#pragma unroll
                for (int nt = 0; nt < 8; nt++) {
                    asm volatile(
                        "mma.sync.aligned.m16n8k16.row.col.f32.f16.f16.f32 "
                        "{%0,%1,%2,%3}, {%4,%5,%6,%7}, {%8,%9}, {%0,%1,%2,%3};\n"
                        : "+f"(c[mt][nt][0]), "+f"(c[mt][nt][1]),
                          "+f"(c[mt][nt][2]), "+f"(c[mt][nt][3])
                        : "r"(af[0]), "r"(af[1]), "r"(af[2]), "r"(af[3]),
                          "r"(bf[nt][0]), "r"(bf[nt][1]));
                }
            }
        }
        __syncthreads();
    }

    // ---- epilogue ----
#pragma unroll
    for (int mt = 0; mt < 4; mt++) {
        int row0 = bm + warpM * 64 + mt * 16 + gr;
#pragma unroll
        for (int nt = 0; nt < 8; nt++) {
            int col = bn + warpN * 64 + nt * 8 + 2 * kq;
            if (col >= N) continue;
            float bz0 = bias ? bias[col] : 0.f;
            float bz1 = bias ? bias[col + 1] : 0.f;
            float v00 = c[mt][nt][0] + bz0, v01 = c[mt][nt][1] + bz1;
            float v10 = c[mt][nt][2] + bz0, v11 = c[mt][nt][3] + bz1;
            if (sizeof(OutT) == 4) {
                *(float2*)((float*)C + (size_t)row0 * N + col) = make_float2(v00, v01);
                *(float2*)((float*)C + (size_t)(row0 + 8) * N + col) = make_float2(v10, v11);
            } else {
                *(__half2*)((__half*)C + (size_t)row0 * N + col) = __floats2half2_rn(v00, v01);
                *(__half2*)((__half*)C + (size_t)(row0 + 8) * N + col) = __floats2half2_rn(v10, v11);
            }
        }
    }
}

// ---------------- A-message passing: grid (Bsz, 2, 2) ----------------
__global__ void __launch_bounds__(128) amsg_kernel(const float* __restrict__ A) {
    int b = blockIdx.x;
    int half = blockIdx.y;
    int chunk = blockIdx.z;
    int t = threadIdx.x;
    __shared__ float hs[Nn][128];
    __shared__ float As[Nn][Nn];
    {
        const __half* base = g_tcat + (size_t)b * Nn * (2 * Hh) + half * Hh + chunk * 128;
        for (int i = t; i < Nn * 16; i += 128) {      // 512 chunks of 8 halves
            int j = i >> 4, c8 = i & 15;
            float4 hv = *(const float4*)(base + (size_t)j * (2 * Hh) + c8 * 8);
            __half2* hp = (__half2*)&hv;
            float2 f0 = __half22float2(hp[0]), f1 = __half22float2(hp[1]);
            float2 f2 = __half22float2(hp[2]), f3 = __half22float2(hp[3]);
            hs[j][c8 * 8 + 0] = f0.x; hs[j][c8 * 8 + 1] = f0.y;
            hs[j][c8 * 8 + 2] = f1.x; hs[j][c8 * 8 + 3] = f1.y;
            hs[j][c8 * 8 + 4] = f2.x; hs[j][c8 * 8 + 5] = f2.y;
            hs[j][c8 * 8 + 6] = f3.x; hs[j][c8 * 8 + 7] = f3.y;
        }
    }
    for (int i = t; i < Nn * Nn; i += 128) {
        int r = i >> 5, cc = i & 31;
        As[r][cc] = A[(size_t)b * Nn * 2 * Nn + r * 2 * Nn + half * Nn + cc];
    }
    __syncthreads();
#pragma unroll 4
    for (int i = 0; i < Nn; i++) {
        float s = 0.f;
#pragma unroll
        for (int j = 0; j < Nn; j++) s = fmaf(As[i][j], hs[j][t], s);
        g_ah[((size_t)b * Nn + i) * (2 * Hh) + half * Hh + chunk * 128 + t] = __float2half_rn(s);
    }
}

// ---------------- GRU cell ----------------
__global__ void gru_kernel() {
    int idx = blockIdx.x * blockDim.x + threadIdx.x;
    int row = idx >> 8;
    int cc = idx & 255;
    size_t base = (size_t)row * (3 * Hh) + cc;
    float ir = g_gi[base], iz = g_gi[base + Hh], inn = g_gi[base + 2 * Hh];
    float hr = g_gh[base], hz = g_gh[base + Hh], hn = g_gh[base + 2 * Hh];
    float r = 1.f / (1.f + expf(-(ir + hr)));
    float z = 1.f / (1.f + expf(-(iz + hz)));
    float ng = tanhf(inn + r * hn);
    float hv = __half2float(g_hh[idx]);
    g_hh[idx] = __float2half_rn(ng + z * (hv - ng));
}

// ---------------- sequence gather + tail ----------------
__global__ void gather_kernel(const int* __restrict__ alias, const int* __restrict__ mask) {
    int b = blockIdx.x;
    int t = threadIdx.x;
    __shared__ int sm_tail;
    if (t == 0) {
        int s = 0;
        for (int l = 0; l < Ll; l++) s += mask[b * Ll + l];
        sm_tail = s - 1;
    }
    __syncthreads();
    int tail = sm_tail;
    for (int l = 0; l < Ll; l++) {
        int a = alias[b * Ll + l];
        __half v = g_hh[((size_t)b * Nn + a) * Hh + t];
        g_hseqs[((size_t)b * Ll + l) * Hh + t] = v;
        if (l == tail) g_htail[(size_t)b * Hh + t] = v;
    }
}

// ---------------- alpha ----------------
__global__ void alpha_kernel(const float* __restrict__ fc3_w) {
    int bl = blockIdx.x;
    int b = bl / Ll;
    int t = threadIdx.x;
    float x = g_q1[(size_t)b * Hh + t] + g_q2[(size_t)bl * Hh + t];
    float v = (1.f / (1.f + expf(-x))) * fc3_w[t];
    __shared__ float red[8];
#pragma unroll
    for (int o = 16; o > 0; o >>= 1) v += __shfl_down_sync(0xffffffff, v, o);
    if ((t & 31) == 0) red[t >> 5] = v;
    __syncthreads();
    if (t == 0) {
        float s = 0.f;
#pragma unroll
        for (int w = 0; w < 8; w++) s += red[w];
        g_alpha[bl] = s;
    }
}

// ---------------- seq_emb -> half ----------------
__global__ void seqemb_kernel(const int* __restrict__ mask) {
    int b = blockIdx.x;
    int t = threadIdx.x;
    float s = 0.f;
    for (int l = 0; l < Ll; l++) {
        float m = (float)mask[b * Ll + l];
        s = fmaf(g_alpha[b * Ll + l] * m,
                 __half2float(g_hseqs[((size_t)b * Ll + l) * Hh + t]), s);
    }
    g_semb[(size_t)b * Hh + t] = __float2half_rn(s);
}

// ---------------- host launcher ----------------
extern "C" void kernel_launch(void* const* d_in, const int* in_sizes, int n_in,
                              void* d_out, int out_size)
{
    const float* A     = (const float*)d_in[0];
    const int*   items = (const int*)d_in[1];
    const int*   alias = (const int*)d_in[2];
    const int*   mask  = (const int*)d_in[3];
    const float* emb   = (const float*)d_in[4];
    const float* W_in  = (const float*)d_in[5];
    const float* b_in  = (const float*)d_in[6];
    const float* W_out = (const float*)d_in[7];
    const float* b_out = (const float*)d_in[8];
    const float* W_ih  = (const float*)d_in[9];
    const float* b_ih  = (const float*)d_in[10];
    const float* W_hh  = (const float*)d_in[11];
    const float* b_hh  = (const float*)d_in[12];
    const float* fc1_w = (const float*)d_in[13];
    const float* fc1_b = (const float*)d_in[14];
    const float* fc2_w = (const float*)d_in[15];
    const float* fc2_b = (const float*)d_in[16];
    const float* fc3_w = (const float*)d_in[17];
    float* out = (float*)d_out;

    __half *hh, *ah, *tcat, *hseqs, *htail, *semb, *wcat, *wih, *whh, *wf1, *wf2, *embh;
    float *gi, *gh, *q1, *q2, *bcat;
    cudaGetSymbolAddress((void**)&hh,    g_hh);
    cudaGetSymbolAddress((void**)&ah,    g_ah);
    cudaGetSymbolAddress((void**)&tcat,  g_tcat);
    cudaGetSymbolAddress((void**)&hseqs, g_hseqs);
    cudaGetSymbolAddress((void**)&htail, g_htail);
    cudaGetSymbolAddress((void**)&semb,  g_semb);
    cudaGetSymbolAddress((void**)&wcat,  g_wcat);
    cudaGetSymbolAddress((void**)&wih,   g_wih);
    cudaGetSymbolAddress((void**)&whh,   g_whh);
    cudaGetSymbolAddress((void**)&wf1,   g_wf1);
    cudaGetSymbolAddress((void**)&wf2,   g_wf2);
    cudaGetSymbolAddress((void**)&embh,  g_embh);
    cudaGetSymbolAddress((void**)&gi,    g_gi);
    cudaGetSymbolAddress((void**)&gh,    g_gh);
    cudaGetSymbolAddress((void**)&q1,    g_q1);
    cudaGetSymbolAddress((void**)&q2,    g_q2);
    cudaGetSymbolAddress((void**)&bcat,  g_bcat);

    cudaFuncSetAttribute(hgemm<float>,  cudaFuncAttributeMaxDynamicSharedMemorySize, GSM_BYTES);
    cudaFuncSetAttribute(hgemm<__half>, cudaFuncAttributeMaxDynamicSharedMemorySize, GSM_BYTES);

    const int MN = Bsz * Nn;   // 16384
    dim3 tb(32, 8);

    // 0. operand preparation
    transpose_h<<<dim3(8, 8),   tb>>>(W_in,  wcat,           Hh, Hh);
    transpose_h<<<dim3(8, 8),   tb>>>(W_out, wcat + Hh * Hh, Hh, Hh);
    transpose_h<<<dim3(24, 16), tb>>>(W_ih, wih, 2 * Hh, 3 * Hh);
    transpose_h<<<dim3(24, 8),  tb>>>(W_hh, whh, Hh, 3 * Hh);
    transpose_h<<<dim3(8, 8),   tb>>>(fc1_w, wf1, Hh, Hh);
    transpose_h<<<dim3(8, 8),   tb>>>(fc2_w, wf2, Hh, Hh);
    embconv_kernel<<<(Vv * Hh / 4 + 255) / 256, 256>>>(emb);
    bcat_kernel<<<2, 256>>>(b_in, b_out);

    auto gemmF = [](const __half* X, const __half* W, const float* bias, float* C,
                    int M, int N, int K) {
        dim3 grid((N + 127) / 128, M / 256);
        hgemm<float><<<grid, 256, GSM_BYTES>>>(X, W, bias, C, M, N, K);
    };
    auto gemmH = [](const __half* X, const __half* W, const float* bias, __half* C,
                    int M, int N, int K) {
        dim3 grid((N + 127) / 128, M / 256);
        hgemm<__half><<<grid, 256, GSM_BYTES>>>(X, W, bias, C, M, N, K);
    };

    // 1. h = emb[items]
    embed_kernel<<<MN, Hh>>>(emb, items);
    // 2. tcat = h @ [W_in|W_out] + [b_in|b_out]   (half out)
    gemmH(hh, wcat, bcat, tcat, MN, 2 * Hh, Hh);
    // 3. a = [A_in@tin | A_out@tout]
    amsg_kernel<<<dim3(Bsz, 2, 2), 128>>>(A);
    // 4. gi = a@W_ih+b_ih ; gh = h@W_hh+b_hh
    gemmF(ah, wih, b_ih, gi, MN, 3 * Hh, 2 * Hh);
    gemmF(hh, whh, b_hh, gh, MN, 3 * Hh, Hh);
    // 5. GRU update
    gru_kernel<<<MN * Hh / 256, 256>>>();
    // 6. gather
    gather_kernel<<<Bsz, Hh>>>(alias, mask);
    // 7. q1, q2
    gemmF(htail, wf1, fc1_b, q1, Bsz, Hh, Hh);
    gemmF(hseqs, wf2, fc2_b, q2, Bsz * Ll, Hh, Hh);
    // 8. alpha ; seq_emb
    alpha_kernel<<<Bsz * Ll, Hh>>>(fc3_w);
    seqemb_kernel<<<Bsz, Hh>>>(mask);
    // 9. out = seq_emb @ emb[1:].T
    gemmF(semb, embh, nullptr, out, Bsz, Vv, Hh);
}

// round 9
// speedup vs baseline: 1.1196x; 1.1196x over previous
#include <cuda_runtime.h>
#include <cuda_fp16.h>
#include <math.h>
#include <stdint.h>

// Problem constants
#define Bsz   512
#define Nn    32
#define Ll    50
#define Hh    256
#define Vv    100000

// ---------------- scratch ----------------
__device__ __align__(256) __half g_hh[Bsz * Nn * Hh];            // node states
__device__ __align__(256) __half g_ah[Bsz * Nn * 2 * Hh];        // GRU input a
__device__ __align__(256) __half g_tcat[Bsz * Nn * 2 * Hh];      // [tin|tout] (half)
__device__ __align__(256) __half g_hseqs[Bsz * Ll * Hh];
__device__ __align__(256) __half g_htail[Bsz * Hh];
__device__ __align__(256) __half g_semb[Bsz * Hh];
__device__ __align__(256) __half g_wcat[512 * Hh];               // [W_in^T ; W_out^T], [N][K]
__device__ __align__(256) __half g_wih[3 * Hh * 2 * Hh];         // [768][512]
__device__ __align__(256) __half g_whh[3 * Hh * Hh];             // [768][256]
__device__ __align__(256) __half g_wf1[Hh * Hh];
__device__ __align__(256) __half g_wf2[Hh * Hh];
__device__ __align__(256) __half g_embh[Vv * Hh];                // emb[1:] in half
// f32 intermediates
__device__ __align__(256) float g_gi[Bsz * Nn * 3 * Hh];
__device__ __align__(256) float g_gh[Bsz * Nn * 3 * Hh];
__device__ __align__(256) float g_q1[Bsz * Hh];
__device__ __align__(256) float g_q2[Bsz * Ll * Hh];
__device__ __align__(256) float g_alpha[Bsz * Ll];
__device__ __align__(256) float g_bcat[2 * Hh];

__device__ __forceinline__ void cpa16(void* dst, const void* src, bool pred) {
    uint32_t d = (uint32_t)__cvta_generic_to_shared(dst);
    int sz = pred ? 16 : 0;
    asm volatile("cp.async.cg.shared.global [%0], [%1], 16, %2;\n"
                 :: "r"(d), "l"(src), "r"(sz));
}
__device__ __forceinline__ void cpa_commit() {
    asm volatile("cp.async.commit_group;\n");
}
__device__ __forceinline__ uint32_t s2u(const void* p) {
    return (uint32_t)__cvta_generic_to_shared(p);
}

// ---------------- weight transpose + halve: src f32 [R][C] -> dst half [C][R] ----------------
__global__ void transpose_h(const float* __restrict__ src, __half* __restrict__ dst,
                            int R, int C) {
    __shared__ float t[32][33];
    int bx = blockIdx.x * 32, by = blockIdx.y * 32;
#pragma unroll
    for (int i = 0; i < 4; i++) {
        int r = by + threadIdx.y + i * 8, c = bx + threadIdx.x;
        if (r < R && c < C) t[threadIdx.y + i * 8][threadIdx.x] = src[(size_t)r * C + c];
    }
    __syncthreads();
#pragma unroll
    for (int i = 0; i < 4; i++) {
        int c = bx + threadIdx.y + i * 8, r = by + threadIdx.x;
        if (c < C && r < R)
            dst[(size_t)c * R + r] = __float2half_rn(t[threadIdx.x][threadIdx.y + i * 8]);
    }
}

// ---------------- emb[1:] -> half ----------------
__global__ void embconv_kernel(const float* __restrict__ emb) {
    size_t i = ((size_t)blockIdx.x * blockDim.x + threadIdx.x) * 4;
    if (i < (size_t)Vv * Hh) {
        float4 v = *(const float4*)(emb + Hh + i);
        __half2* d = (__half2*)(g_embh + i);
        d[0] = __floats2half2_rn(v.x, v.y);
        d[1] = __floats2half2_rn(v.z, v.w);
    }
}

__global__ void bcat_kernel(const float* __restrict__ b_in, const float* __restrict__ b_out) {
    int i = threadIdx.x + blockIdx.x * blockDim.x;
    if (i < 2 * Hh) g_bcat[i] = (i < Hh) ? b_in[i] : b_out[i - Hh];
}

// ---------------- embedding gather -> half ----------------
__global__ void embed_kernel(const float* __restrict__ emb, const int* __restrict__ items) {
    int bn = blockIdx.x;
    int t = threadIdx.x;
    int item = items[bn];
    g_hh[(size_t)bn * Hh + t] = __float2half_rn(emb[(size_t)item * Hh + t]);
}

// ---------------- fp16 tensor-core GEMM (128x128 tile, ldmatrix) ----------------
// C[M,N] = A[M,K] @ B^T (+bias). A:[M][K] half. B:[N][K] half.
// BM=BN=128, BK=32, 256 threads, 8 warps (2x4 -> 64x32 warp tiles), 3-stage cp.async.
// Requires M%128==0, K%32==0. N guarded.
#define LDAh 40                        // halves per smem row (80B) - conflict-free
#define STGH 10240                     // halves per stage (A 5120 + B 5120)
#define GSM_BYTES (3 * STGH * 2)       // 61440 B -> 2 CTAs/SM
template <typename OutT>
__global__ void __launch_bounds__(256, 2) hgemm(
    const __half* __restrict__ A, const __half* __restrict__ B,
    const float* __restrict__ bias, OutT* __restrict__ C,
    int M, int N, int K)
{
    extern __shared__ __half sm[];
    const int tid = threadIdx.x, wid = tid >> 5, lane = tid & 31;
    const int bm = blockIdx.y * 128;
    const int bn = blockIdx.x * 128;
    const int warpM = wid >> 2, warpN = wid & 3;   // 2x4 -> 64x32
    const int gr = lane >> 2, kq = lane & 3;
    const int lr7 = lane & 7, lb8 = (lane >> 3) & 1, lb16 = (lane >> 4) & 1;
    const int T = K >> 5;

    float c[4][4][4];
#pragma unroll
    for (int i = 0; i < 4; i++)
#pragma unroll
        for (int j = 0; j < 4; j++)
#pragma unroll
            for (int r = 0; r < 4; r++) c[i][j][r] = 0.f;

    auto load_stage = [&](int kt, int s) {
        __half* stg = sm + s * STGH;
#pragma unroll
        for (int i = 0; i < 2; i++) {
            int ci = tid + i * 256;            // A: 512 16B chunks
            int row = ci >> 2, q = ci & 3;
            cpa16(stg + row * LDAh + q * 8,
                  A + (size_t)(bm + row) * K + kt * 32 + q * 8, true);
        }
#pragma unroll
        for (int i = 0; i < 2; i++) {
            int ci = tid + i * 256;            // B: 512 16B chunks
            int row = ci >> 2, q = ci & 3;
            cpa16(stg + 5120 + row * LDAh + q * 8,
                  B + (size_t)(bn + row) * K + kt * 32 + q * 8, (bn + row) < N);
        }
        cpa_commit();
    };

    load_stage(0, 0);
    load_stage(1, 1);

    for (int it = 0; it < T; it++) {
        if (it + 2 < T) load_stage(it + 2, (it + 2) % 3);
        if (it + 2 < T)      asm volatile("cp.async.wait_group 2;\n" ::: "memory");
        else if (it + 1 < T) asm volatile("cp.async.wait_group 1;\n" ::: "memory");
        else                 asm volatile("cp.async.wait_group 0;\n" ::: "memory");
        __syncthreads();

        const __half* as = sm + (it % 3) * STGH;
        const uint32_t aB = s2u(as);
        const uint32_t bB = aB + 5120 * 2;
#pragma unroll
        for (int ks = 0; ks < 2; ks++) {
            const int kb = ks * 16;
            // B fragments: 32 cols = 2 ldmatrix.x4 (16 n-rows each)
            uint32_t bf[4][2];
#pragma unroll
            for (int ntp = 0; ntp < 2; ntp++) {
                uint32_t addr = bB + (uint32_t)(
                    (warpN * 32 + ntp * 16 + lr7 + lb16 * 8) * LDAh + kb + lb8 * 8) * 2;
                asm volatile("ldmatrix.sync.aligned.m8n8.x4.shared.b16 {%0,%1,%2,%3}, [%4];"
                             : "=r"(bf[2 * ntp][0]), "=r"(bf[2 * ntp][1]),
                               "=r"(bf[2 * ntp + 1][0]), "=r"(bf[2 * ntp + 1][1])
                             : "r"(addr));
            }
            // A fragments: 64 rows = 4 ldmatrix.x4 (16 m-rows each)
#pragma unroll
            for (int mt = 0; mt < 4; mt++) {
                uint32_t af[4];
                uint32_t addr = aB + (uint32_t)(
                    (warpM * 64 + mt * 16 + lr7 + lb8 * 8) * LDAh + kb + lb16 * 8) * 2;
                asm volatile("ldmatrix.sync.aligned.m8n8.x4.shared.b16 {%0,%1,%2,%3}, [%4];"
                             : "=r"(af[0]), "=r"(af[1]), "=r"(af[2]), "=r"(af[3])
                             : "r"(addr));
#pragma unroll
                for (int nt = 0; nt < 4; nt++) {
                    asm volatile(
                        "mma.sync.aligned.m16n8k16.row.col.f32.f16.f16.f32 "
                        "{%0,%1,%2,%3}, {%4,%5,%6,%7}, {%8,%9}, {%0,%1,%2,%3};\n"
                        : "+f"(c[mt][nt][0]), "+f"(c[mt][nt][1]),
                          "+f"(c[mt][nt][2]), "+f"(c[mt][nt][3])
                        : "r"(af[0]), "r"(af[1]), "r"(af[2]), "r"(af[3]),
                          "r"(bf[nt][0]), "r"(bf[nt][1]));
                }
            }
        }
        __syncthreads();
    }

    // ---- epilogue ----
#pragma unroll
    for (int mt = 0; mt < 4; mt++) {
        int row0 = bm + warpM * 64 + mt * 16 + gr;
#pragma unroll
        for (int nt = 0; nt < 4; nt++) {
            int col = bn + warpN * 32 + nt * 8 + 2 * kq;
            if (col >= N) continue;
            float bz0 = bias ? bias[col] : 0.f;
            float bz1 = bias ? bias[col + 1] : 0.f;
            float v00 = c[mt][nt][0] + bz0, v01 = c[mt][nt][1] + bz1;
            float v10 = c[mt][nt][2] + bz0, v11 = c[mt][nt][3] + bz1;
            if (sizeof(OutT) == 4) {
                *(float2*)((float*)C + (size_t)row0 * N + col) = make_float2(v00, v01);
                *(float2*)((float*)C + (size_t)(row0 + 8) * N + col) = make_float2(v10, v11);
            } else {
                *(__half2*)((__half*)C + (size_t)row0 * N + col) = __floats2half2_rn(v00, v01);
                *(__half2*)((__half*)C + (size_t)(row0 + 8) * N + col) = __floats2half2_rn(v10, v11);
            }
        }
    }
}

// ---------------- A-message passing: grid (Bsz, 2, 2) ----------------
__global__ void __launch_bounds__(128) amsg_kernel(const float* __restrict__ A) {
    int b = blockIdx.x;
    int half = blockIdx.y;
    int chunk = blockIdx.z;
    int t = threadIdx.x;
    __shared__ float hs[Nn][128];
    __shared__ float As[Nn][Nn];
    {
        const __half* base = g_tcat + (size_t)b * Nn * (2 * Hh) + half * Hh + chunk * 128;
        for (int i = t; i < Nn * 16; i += 128) {      // 512 chunks of 8 halves
            int j = i >> 4, c8 = i & 15;
            float4 hv = *(const float4*)(base + (size_t)j * (2 * Hh) + c8 * 8);
            __half2* hp = (__half2*)&hv;
            float2 f0 = __half22float2(hp[0]), f1 = __half22float2(hp[1]);
            float2 f2 = __half22float2(hp[2]), f3 = __half22float2(hp[3]);
            hs[j][c8 * 8 + 0] = f0.x; hs[j][c8 * 8 + 1] = f0.y;
            hs[j][c8 * 8 + 2] = f1.x; hs[j][c8 * 8 + 3] = f1.y;
            hs[j][c8 * 8 + 4] = f2.x; hs[j][c8 * 8 + 5] = f2.y;
            hs[j][c8 * 8 + 6] = f3.x; hs[j][c8 * 8 + 7] = f3.y;
        }
    }
    for (int i = t; i < Nn * Nn; i += 128) {
        int r = i >> 5, cc = i & 31;
        As[r][cc] = A[(size_t)b * Nn * 2 * Nn + r * 2 * Nn + half * Nn + cc];
    }
    __syncthreads();
#pragma unroll 4
    for (int i = 0; i < Nn; i++) {
        float s = 0.f;
#pragma unroll
        for (int j = 0; j < Nn; j++) s = fmaf(As[i][j], hs[j][t], s);
        g_ah[((size_t)b * Nn + i) * (2 * Hh) + half * Hh + chunk * 128 + t] = __float2half_rn(s);
    }
}

// ---------------- GRU cell ----------------
__global__ void gru_kernel() {
    int idx = blockIdx.x * blockDim.x + threadIdx.x;
    int row = idx >> 8;
    int cc = idx & 255;
    size_t base = (size_t)row * (3 * Hh) + cc;
    float ir = g_gi[base], iz = g_gi[base + Hh], inn = g_gi[base + 2 * Hh];
    float hr = g_gh[base], hz = g_gh[base + Hh], hn = g_gh[base + 2 * Hh];
    float r = 1.f / (1.f + expf(-(ir + hr)));
    float z = 1.f / (1.f + expf(-(iz + hz)));
    float ng = tanhf(inn + r * hn);
    float hv = __half2float(g_hh[idx]);
    g_hh[idx] = __float2half_rn(ng + z * (hv - ng));
}

// ---------------- sequence gather + tail ----------------
__global__ void gather_kernel(const int* __restrict__ alias, const int* __restrict__ mask) {
    int b = blockIdx.x;
    int t = threadIdx.x;
    __shared__ int sm_tail;
    if (t == 0) {
        int s = 0;
        for (int l = 0; l < Ll; l++) s += mask[b * Ll + l];
        sm_tail = s - 1;
    }
    __syncthreads();
    int tail = sm_tail;
    for (int l = 0; l < Ll; l++) {
        int a = alias[b * Ll + l];
        __half v = g_hh[((size_t)b * Nn + a) * Hh + t];
        g_hseqs[((size_t)b * Ll + l) * Hh + t] = v;
        if (l == tail) g_htail[(size_t)b * Hh + t] = v;
    }
}

// ---------------- alpha ----------------
__global__ void alpha_kernel(const float* __restrict__ fc3_w) {
    int bl = blockIdx.x;
    int b = bl / Ll;
    int t = threadIdx.x;
    float x = g_q1[(size_t)b * Hh + t] + g_q2[(size_t)bl * Hh + t];
    float v = (1.f / (1.f + expf(-x))) * fc3_w[t];
    __shared__ float red[8];
#pragma unroll
    for (int o = 16; o > 0; o >>= 1) v += __shfl_down_sync(0xffffffff, v, o);
    if ((t & 31) == 0) red[t >> 5] = v;
    __syncthreads();
    if (t == 0) {
        float s = 0.f;
#pragma unroll
        for (int w = 0; w < 8; w++) s += red[w];
        g_alpha[bl] = s;
    }
}

// ---------------- seq_emb -> half ----------------
__global__ void seqemb_kernel(const int* __restrict__ mask) {
    int b = blockIdx.x;
    int t = threadIdx.x;
    float s = 0.f;
    for (int l = 0; l < Ll; l++) {
        float m = (float)mask[b * Ll + l];
        s = fmaf(g_alpha[b * Ll + l] * m,
                 __half2float(g_hseqs[((size_t)b * Ll + l) * Hh + t]), s);
    }
    g_semb[(size_t)b * Hh + t] = __float2half_rn(s);
}

// ---------------- host launcher ----------------
extern "C" void kernel_launch(void* const* d_in, const int* in_sizes, int n_in,
                              void* d_out, int out_size)
{
    const float* A     = (const float*)d_in[0];
    const int*   items = (const int*)d_in[1];
    const int*   alias = (const int*)d_in[2];
    const int*   mask  = (const int*)d_in[3];
    const float* emb   = (const float*)d_in[4];
    const float* W_in  = (const float*)d_in[5];
    const float* b_in  = (const float*)d_in[6];
    const float* W_out = (const float*)d_in[7];
    const float* b_out = (const float*)d_in[8];
    const float* W_ih  = (const float*)d_in[9];
    const float* b_ih  = (const float*)d_in[10];
    const float* W_hh  = (const float*)d_in[11];
    const float* b_hh  = (const float*)d_in[12];
    const float* fc1_w = (const float*)d_in[13];
    const float* fc1_b = (const float*)d_in[14];
    const float* fc2_w = (const float*)d_in[15];
    const float* fc2_b = (const float*)d_in[16];
    const float* fc3_w = (const float*)d_in[17];
    float* out = (float*)d_out;

    __half *hh, *ah, *tcat, *hseqs, *htail, *semb, *wcat, *wih, *whh, *wf1, *wf2, *embh;
    float *gi, *gh, *q1, *q2, *bcat;
    cudaGetSymbolAddress((void**)&hh,    g_hh);
    cudaGetSymbolAddress((void**)&ah,    g_ah);
    cudaGetSymbolAddress((void**)&tcat,  g_tcat);
    cudaGetSymbolAddress((void**)&hseqs, g_hseqs);
    cudaGetSymbolAddress((void**)&htail, g_htail);
    cudaGetSymbolAddress((void**)&semb,  g_semb);
    cudaGetSymbolAddress((void**)&wcat,  g_wcat);
    cudaGetSymbolAddress((void**)&wih,   g_wih);
    cudaGetSymbolAddress((void**)&whh,   g_whh);
    cudaGetSymbolAddress((void**)&wf1,   g_wf1);
    cudaGetSymbolAddress((void**)&wf2,   g_wf2);
    cudaGetSymbolAddress((void**)&embh,  g_embh);
    cudaGetSymbolAddress((void**)&gi,    g_gi);
    cudaGetSymbolAddress((void**)&gh,    g_gh);
    cudaGetSymbolAddress((void**)&q1,    g_q1);
    cudaGetSymbolAddress((void**)&q2,    g_q2);
    cudaGetSymbolAddress((void**)&bcat,  g_bcat);

    cudaFuncSetAttribute(hgemm<float>,  cudaFuncAttributeMaxDynamicSharedMemorySize, GSM_BYTES);
    cudaFuncSetAttribute(hgemm<__half>, cudaFuncAttributeMaxDynamicSharedMemorySize, GSM_BYTES);

    const int MN = Bsz * Nn;   // 16384
    dim3 tb(32, 8);

    // 0. operand preparation
    transpose_h<<<dim3(8, 8),   tb>>>(W_in,  wcat,           Hh, Hh);
    transpose_h<<<dim3(8, 8),   tb>>>(W_out, wcat + Hh * Hh, Hh, Hh);
    transpose_h<<<dim3(24, 16), tb>>>(W_ih, wih, 2 * Hh, 3 * Hh);
    transpose_h<<<dim3(24, 8),  tb>>>(W_hh, whh, Hh, 3 * Hh);
    transpose_h<<<dim3(8, 8),   tb>>>(fc1_w, wf1, Hh, Hh);
    transpose_h<<<dim3(8, 8),   tb>>>(fc2_w, wf2, Hh, Hh);
    embconv_kernel<<<(Vv * Hh / 4 + 255) / 256, 256>>>(emb);
    bcat_kernel<<<2, 256>>>(b_in, b_out);

    auto gemmF = [](const __half* X, const __half* W, const float* bias, float* C,
                    int M, int N, int K) {
        dim3 grid((N + 127) / 128, M / 128);
        hgemm<float><<<grid, 256, GSM_BYTES>>>(X, W, bias, C, M, N, K);
    };
    auto gemmH = [](const __half* X, const __half* W, const float* bias, __half* C,
                    int M, int N, int K) {
        dim3 grid((N + 127) / 128, M / 128);
        hgemm<__half><<<grid, 256, GSM_BYTES>>>(X, W, bias, C, M, N, K);
    };

    // 1. h = emb[items]
    embed_kernel<<<MN, Hh>>>(emb, items);
    // 2. tcat = h @ [W_in|W_out] + [b_in|b_out]   (half out)
    gemmH(hh, wcat, bcat, tcat, MN, 2 * Hh, Hh);
    // 3. a = [A_in@tin | A_out@tout]
    amsg_kernel<<<dim3(Bsz, 2, 2), 128>>>(A);
    // 4. gi = a@W_ih+b_ih ; gh = h@W_hh+b_hh
    gemmF(ah, wih, b_ih, gi, MN, 3 * Hh, 2 * Hh);
    gemmF(hh, whh, b_hh, gh, MN, 3 * Hh, Hh);
    // 5. GRU update
    gru_kernel<<<MN * Hh / 256, 256>>>();
    // 6. gather
    gather_kernel<<<Bsz, Hh>>>(alias, mask);
    // 7. q1, q2
    gemmF(htail, wf1, fc1_b, q1, Bsz, Hh, Hh);
    gemmF(hseqs, wf2, fc2_b, q2, Bsz * Ll, Hh, Hh);
    // 8. alpha ; seq_emb
    alpha_kernel<<<Bsz * Ll, Hh>>>(fc3_w);
    seqemb_kernel<<<Bsz, Hh>>>(mask);
    // 9. out = seq_emb @ emb[1:].T
    gemmF(semb, embh, nullptr, out, Bsz, Vv, Hh);
}

// round 14
// speedup vs baseline: 1.2219x; 1.0914x over previous
#include <cuda_runtime.h>
#include <cuda_fp16.h>
#include <math.h>
#include <stdint.h>

// Problem constants
#define Bsz   512
#define Nn    32
#define Ll    50
#define Hh    256
#define Vv    100000

// ---------------- scratch ----------------
__device__ __align__(256) __half g_hh[Bsz * Nn * Hh];            // node states
__device__ __align__(256) __half g_ah[Bsz * Nn * 2 * Hh];        // GRU input a
__device__ __align__(256) __half g_tcat[Bsz * Nn * 2 * Hh];      // [tin|tout] (half)
__device__ __align__(256) __half g_hseqs[Bsz * Ll * Hh];
__device__ __align__(256) __half g_htail[Bsz * Hh];
__device__ __align__(256) __half g_semb[Bsz * Hh];
__device__ __align__(256) __half g_wcat[512 * Hh];               // [W_in^T ; W_out^T], [N][K]
__device__ __align__(256) __half g_wih[3 * Hh * 2 * Hh];         // [768][512]
__device__ __align__(256) __half g_whh[3 * Hh * Hh];             // [768][256]
__device__ __align__(256) __half g_wf1[Hh * Hh];
__device__ __align__(256) __half g_wf2[Hh * Hh];
__device__ __align__(256) __half g_embh[Vv * Hh];                // emb[1:] in half
// f32 intermediates
__device__ __align__(256) float g_gi[Bsz * Nn * 3 * Hh];
__device__ __align__(256) float g_gh[Bsz * Nn * 3 * Hh];
__device__ __align__(256) float g_q1[Bsz * Hh];
__device__ __align__(256) float g_q2[Bsz * Ll * Hh];
__device__ __align__(256) float g_alpha[Bsz * Ll];
__device__ __align__(256) float g_bcat[2 * Hh];

__device__ __forceinline__ void cpa16(void* dst, const void* src, bool pred) {
    uint32_t d = (uint32_t)__cvta_generic_to_shared(dst);
    int sz = pred ? 16 : 0;
    asm volatile("cp.async.cg.shared.global [%0], [%1], 16, %2;\n"
                 :: "r"(d), "l"(src), "r"(sz));
}
__device__ __forceinline__ void cpa_commit() {
    asm volatile("cp.async.commit_group;\n");
}
__device__ __forceinline__ uint32_t s2u(const void* p) {
    return (uint32_t)__cvta_generic_to_shared(p);
}

// ---------------- fused weight transpose + halve (all 6 weights, one launch) ----------------
__global__ void transpose_all(const float* __restrict__ W_in, const float* __restrict__ W_out,
                              const float* __restrict__ W_ih, const float* __restrict__ W_hh,
                              const float* __restrict__ fc1_w, const float* __restrict__ fc2_w) {
    const float* src; __half* dst; int R, C;
    switch (blockIdx.z) {
        case 0:  src = W_in;  dst = g_wcat;           R = Hh;     C = Hh;     break;
        case 1:  src = W_out; dst = g_wcat + Hh * Hh; R = Hh;     C = Hh;     break;
        case 2:  src = W_ih;  dst = g_wih;            R = 2 * Hh; C = 3 * Hh; break;
        case 3:  src = W_hh;  dst = g_whh;            R = Hh;     C = 3 * Hh; break;
        case 4:  src = fc1_w; dst = g_wf1;            R = Hh;     C = Hh;     break;
        default: src = fc2_w; dst = g_wf2;            R = Hh;     C = Hh;     break;
    }
    int bx = blockIdx.x * 32, by = blockIdx.y * 32;
    if (bx >= C || by >= R) return;
    __shared__ float t[32][33];
#pragma unroll
    for (int i = 0; i < 4; i++) {
        int r = by + threadIdx.y + i * 8, c = bx + threadIdx.x;
        if (r < R && c < C) t[threadIdx.y + i * 8][threadIdx.x] = src[(size_t)r * C + c];
    }
    __syncthreads();
#pragma unroll
    for (int i = 0; i < 4; i++) {
        int c = bx + threadIdx.y + i * 8, r = by + threadIdx.x;
        if (c < C && r < R)
            dst[(size_t)c * R + r] = __float2half_rn(t[threadIdx.x][threadIdx.y + i * 8]);
    }
}

// ---------------- emb[1:] -> half ----------------
__global__ void embconv_kernel(const float* __restrict__ emb) {
    size_t i = ((size_t)blockIdx.x * blockDim.x + threadIdx.x) * 4;
    if (i < (size_t)Vv * Hh) {
        float4 v = *(const float4*)(emb + Hh + i);
        __half2* d = (__half2*)(g_embh + i);
        d[0] = __floats2half2_rn(v.x, v.y);
        d[1] = __floats2half2_rn(v.z, v.w);
    }
}

__global__ void bcat_kernel(const float* __restrict__ b_in, const float* __restrict__ b_out) {
    int i = threadIdx.x + blockIdx.x * blockDim.x;
    if (i < 2 * Hh) g_bcat[i] = (i < Hh) ? b_in[i] : b_out[i - Hh];
}

// ---------------- embedding gather -> half ----------------
__global__ void embed_kernel(const float* __restrict__ emb, const int* __restrict__ items) {
    int bn = blockIdx.x;
    int t = threadIdx.x;
    int item = items[bn];
    g_hh[(size_t)bn * Hh + t] = __float2half_rn(emb[(size_t)item * Hh + t]);
}

// ---------------- fp16 tensor-core GEMM (128x128 tile, BK=64, ldmatrix) ----------------
// C[M,N] = A[M,K] @ B^T (+bias). A:[M][K] half. B:[N][K] half.
// 256 threads, 8 warps (2x4 -> 64x32 warp tiles), 3-stage cp.async, BK=64.
// Requires M%128==0, K%64==0. N guarded.
#define LDAh 72                        // halves per smem row (144B): 144%128=16 -> conflict-free
#define ASTG (128 * LDAh)              // 9216 halves
#define STGH (2 * ASTG)                // 18432 halves per stage (36864 B)
#define GSM_BYTES (3 * STGH * 2)       // 110592 B -> 2 CTAs/SM (221184 <= 228KB)
template <typename OutT>
__global__ void __launch_bounds__(256, 2) hgemm(
    const __half* __restrict__ A, const __half* __restrict__ B,
    const float* __restrict__ bias, OutT* __restrict__ C,
    int M, int N, int K)
{
    extern __shared__ __half sm[];
    const int tid = threadIdx.x, wid = tid >> 5, lane = tid & 31;
    const int bm = blockIdx.y * 128;
    const int bn = blockIdx.x * 128;
    const int warpM = wid >> 2, warpN = wid & 3;   // 2x4 -> 64x32
    const int gr = lane >> 2, kq = lane & 3;
    const int lr7 = lane & 7, lb8 = (lane >> 3) & 1, lb16 = (lane >> 4) & 1;
    const int T = K >> 6;

    float c[4][4][4];
#pragma unroll
    for (int i = 0; i < 4; i++)
#pragma unroll
        for (int j = 0; j < 4; j++)
#pragma unroll
            for (int r = 0; r < 4; r++) c[i][j][r] = 0.f;

    auto load_stage = [&](int kt, int s) {
        __half* stg = sm + s * STGH;
#pragma unroll
        for (int i = 0; i < 4; i++) {            // A: 1024 16B chunks (128 rows x 8)
            int ci = tid + i * 256;
            int row = ci >> 3, q = ci & 7;
            cpa16(stg + row * LDAh + q * 8,
                  A + (size_t)(bm + row) * K + kt * 64 + q * 8, true);
        }
#pragma unroll
        for (int i = 0; i < 4; i++) {            // B: 1024 16B chunks
            int ci = tid + i * 256;
            int row = ci >> 3, q = ci & 7;
            cpa16(stg + ASTG + row * LDAh + q * 8,
                  B + (size_t)(bn + row) * K + kt * 64 + q * 8, (bn + row) < N);
        }
        cpa_commit();
    };

    load_stage(0, 0);
    if (T > 1) load_stage(1, 1);

    for (int it = 0; it < T; it++) {
        if (it + 2 < T) load_stage(it + 2, (it + 2) % 3);
        if (it + 2 < T)      asm volatile("cp.async.wait_group 2;\n" ::: "memory");
        else if (it + 1 < T) asm volatile("cp.async.wait_group 1;\n" ::: "memory");
        else                 asm volatile("cp.async.wait_group 0;\n" ::: "memory");
        __syncthreads();

        const __half* as = sm + (it % 3) * STGH;
        const uint32_t aB = s2u(as);
        const uint32_t bB = aB + ASTG * 2;
#pragma unroll
        for (int ks = 0; ks < 4; ks++) {
            const int kb = ks * 16;
            // B fragments: 32 cols = 2 ldmatrix.x4
            uint32_t bf[4][2];
#pragma unroll
            for (int ntp = 0; ntp < 2; ntp++) {
                uint32_t addr = bB + (uint32_t)(
                    (warpN * 32 + ntp * 16 + lr7 + lb16 * 8) * LDAh + kb + lb8 * 8) * 2;
                asm volatile("ldmatrix.sync.aligned.m8n8.x4.shared.b16 {%0,%1,%2,%3}, [%4];"
                             : "=r"(bf[2 * ntp][0]), "=r"(bf[2 * ntp][1]),
                               "=r"(bf[2 * ntp + 1][0]), "=r"(bf[2 * ntp + 1][1])
                             : "r"(addr));
            }
            // A fragments: 64 rows = 4 ldmatrix.x4
#pragma unroll
            for (int mt = 0; mt < 4; mt++) {
                uint32_t af[4];
                uint32_t addr = aB + (uint32_t)(
                    (warpM * 64 + mt * 16 + lr7 + lb8 * 8) * LDAh + kb + lb16 * 8) * 2;
                asm volatile("ldmatrix.sync.aligned.m8n8.x4.shared.b16 {%0,%1,%2,%3}, [%4];"
                             : "=r"(af[0]), "=r"(af[1]), "=r"(af[2]), "=r"(af[3])
                             : "r"(addr));
#pragma unroll
                for (int nt = 0; nt < 4; nt++) {
                    asm volatile(
                        "mma.sync.aligned.m16n8k16.row.col.f32.f16.f16.f32 "
                        "{%0,%1,%2,%3}, {%4,%5,%6,%7}, {%8,%9}, {%0,%1,%2,%3};\n"
                        : "+f"(c[mt][nt][0]), "+f"(c[mt][nt][1]),
                          "+f"(c[mt][nt][2]), "+f"(c[mt][nt][3])
                        : "r"(af[0]), "r"(af[1]), "r"(af[2]), "r"(af[3]),
                          "r"(bf[nt][0]), "r"(bf[nt][1]));
                }
            }
        }
        __syncthreads();
    }

    // ---- epilogue ----
#pragma unroll
    for (int mt = 0; mt < 4; mt++) {
        int row0 = bm + warpM * 64 + mt * 16 + gr;
#pragma unroll
        for (int nt = 0; nt < 4; nt++) {
            int col = bn + warpN * 32 + nt * 8 + 2 * kq;
            if (col >= N) continue;
            float bz0 = bias ? bias[col] : 0.f;
            float bz1 = bias ? bias[col + 1] : 0.f;
            float v00 = c[mt][nt][0] + bz0, v01 = c[mt][nt][1] + bz1;
            float v10 = c[mt][nt][2] + bz0, v11 = c[mt][nt][3] + bz1;
            if (sizeof(OutT) == 4) {
                *(float2*)((float*)C + (size_t)row0 * N + col) = make_float2(v00, v01);
                *(float2*)((float*)C + (size_t)(row0 + 8) * N + col) = make_float2(v10, v11);
            } else {
                *(__half2*)((__half*)C + (size_t)row0 * N + col) = __floats2half2_rn(v00, v01);
                *(__half2*)((__half*)C + (size_t)(row0 + 8) * N + col) = __floats2half2_rn(v10, v11);
            }
        }
    }
}

// ---------------- A-message passing: grid (Bsz, 2, 2) ----------------
__global__ void __launch_bounds__(128) amsg_kernel(const float* __restrict__ A) {
    int b = blockIdx.x;
    int half = blockIdx.y;
    int chunk = blockIdx.z;
    int t = threadIdx.x;
    __shared__ float hs[Nn][128];
    __shared__ float As[Nn][Nn];
    {
        const __half* base = g_tcat + (size_t)b * Nn * (2 * Hh) + half * Hh + chunk * 128;
        for (int i = t; i < Nn * 16; i += 128) {      // 512 chunks of 8 halves
            int j = i >> 4, c8 = i & 15;
            float4 hv = *(const float4*)(base + (size_t)j * (2 * Hh) + c8 * 8);
            __half2* hp = (__half2*)&hv;
            float2 f0 = __half22float2(hp[0]), f1 = __half22float2(hp[1]);
            float2 f2 = __half22float2(hp[2]), f3 = __half22float2(hp[3]);
            hs[j][c8 * 8 + 0] = f0.x; hs[j][c8 * 8 + 1] = f0.y;
            hs[j][c8 * 8 + 2] = f1.x; hs[j][c8 * 8 + 3] = f1.y;
            hs[j][c8 * 8 + 4] = f2.x; hs[j][c8 * 8 + 5] = f2.y;
            hs[j][c8 * 8 + 6] = f3.x; hs[j][c8 * 8 + 7] = f3.y;
        }
    }
    for (int i = t; i < Nn * Nn; i += 128) {
        int r = i >> 5, cc = i & 31;
        As[r][cc] = A[(size_t)b * Nn * 2 * Nn + r * 2 * Nn + half * Nn + cc];
    }
    __syncthreads();
#pragma unroll 4
    for (int i = 0; i < Nn; i++) {
        float s = 0.f;
#pragma unroll
        for (int j = 0; j < Nn; j++) s = fmaf(As[i][j], hs[j][t], s);
        g_ah[((size_t)b * Nn + i) * (2 * Hh) + half * Hh + chunk * 128 + t] = __float2half_rn(s);
    }
}

// ---------------- GRU cell ----------------
__global__ void gru_kernel() {
    int idx = blockIdx.x * blockDim.x + threadIdx.x;
    int row = idx >> 8;
    int cc = idx & 255;
    size_t base = (size_t)row * (3 * Hh) + cc;
    float ir = g_gi[base], iz = g_gi[base + Hh], inn = g_gi[base + 2 * Hh];
    float hr = g_gh[base], hz = g_gh[base + Hh], hn = g_gh[base + 2 * Hh];
    float r = 1.f / (1.f + expf(-(ir + hr)));
    float z = 1.f / (1.f + expf(-(iz + hz)));
    float ng = tanhf(inn + r * hn);
    float hv = __half2float(g_hh[idx]);
    g_hh[idx] = __float2half_rn(ng + z * (hv - ng));
}

// ---------------- sequence gather + tail ----------------
__global__ void gather_kernel(const int* __restrict__ alias, const int* __restrict__ mask) {
    int b = blockIdx.x;
    int t = threadIdx.x;
    __shared__ int sm_tail;
    if (t == 0) {
        int s = 0;
        for (int l = 0; l < Ll; l++) s += mask[b * Ll + l];
        sm_tail = s - 1;
    }
    __syncthreads();
    int tail = sm_tail;
    for (int l = 0; l < Ll; l++) {
        int a = alias[b * Ll + l];
        __half v = g_hh[((size_t)b * Nn + a) * Hh + t];
        g_hseqs[((size_t)b * Ll + l) * Hh + t] = v;
        if (l == tail) g_htail[(size_t)b * Hh + t] = v;
    }
}

// ---------------- alpha ----------------
__global__ void alpha_kernel(const float* __restrict__ fc3_w) {
    int bl = blockIdx.x;
    int b = bl / Ll;
    int t = threadIdx.x;
    float x = g_q1[(size_t)b * Hh + t] + g_q2[(size_t)bl * Hh + t];
    float v = (1.f / (1.f + expf(-x))) * fc3_w[t];
    __shared__ float red[8];
#pragma unroll
    for (int o = 16; o > 0; o >>= 1) v += __shfl_down_sync(0xffffffff, v, o);
    if ((t & 31) == 0) red[t >> 5] = v;
    __syncthreads();
    if (t == 0) {
        float s = 0.f;
#pragma unroll
        for (int w = 0; w < 8; w++) s += red[w];
        g_alpha[bl] = s;
    }
}

// ---------------- seq_emb -> half ----------------
__global__ void seqemb_kernel(const int* __restrict__ mask) {
    int b = blockIdx.x;
    int t = threadIdx.x;
    float s = 0.f;
    for (int l = 0; l < Ll; l++) {
        float m = (float)mask[b * Ll + l];
        s = fmaf(g_alpha[b * Ll + l] * m,
                 __half2float(g_hseqs[((size_t)b * Ll + l) * Hh + t]), s);
    }
    g_semb[(size_t)b * Hh + t] = __float2half_rn(s);
}

// ---------------- host launcher ----------------
extern "C" void kernel_launch(void* const* d_in, const int* in_sizes, int n_in,
                              void* d_out, int out_size)
{
    const float* A     = (const float*)d_in[0];
    const int*   items = (const int*)d_in[1];
    const int*   alias = (const int*)d_in[2];
    const int*   mask  = (const int*)d_in[3];
    const float* emb   = (const float*)d_in[4];
    const float* W_in  = (const float*)d_in[5];
    const float* b_in  = (const float*)d_in[6];
    const float* W_out = (const float*)d_in[7];
    const float* b_out = (const float*)d_in[8];
    const float* W_ih  = (const float*)d_in[9];
    const float* b_ih  = (const float*)d_in[10];
    const float* W_hh  = (const float*)d_in[11];
    const float* b_hh  = (const float*)d_in[12];
    const float* fc1_w = (const float*)d_in[13];
    const float* fc1_b = (const float*)d_in[14];
    const float* fc2_w = (const float*)d_in[15];
    const float* fc2_b = (const float*)d_in[16];
    const float* fc3_w = (const float*)d_in[17];
    float* out = (float*)d_out;

    __half *hh, *ah, *tcat, *hseqs, *htail, *semb, *wcat, *wih, *whh, *wf1, *wf2, *embh;
    float *gi, *gh, *q1, *q2, *bcat;
    cudaGetSymbolAddress((void**)&hh,    g_hh);
    cudaGetSymbolAddress((void**)&ah,    g_ah);
    cudaGetSymbolAddress((void**)&tcat,  g_tcat);
    cudaGetSymbolAddress((void**)&hseqs, g_hseqs);
    cudaGetSymbolAddress((void**)&htail, g_htail);
    cudaGetSymbolAddress((void**)&semb,  g_semb);
    cudaGetSymbolAddress((void**)&wcat,  g_wcat);
    cudaGetSymbolAddress((void**)&wih,   g_wih);
    cudaGetSymbolAddress((void**)&whh,   g_whh);
    cudaGetSymbolAddress((void**)&wf1,   g_wf1);
    cudaGetSymbolAddress((void**)&wf2,   g_wf2);
    cudaGetSymbolAddress((void**)&embh,  g_embh);
    cudaGetSymbolAddress((void**)&gi,    g_gi);
    cudaGetSymbolAddress((void**)&gh,    g_gh);
    cudaGetSymbolAddress((void**)&q1,    g_q1);
    cudaGetSymbolAddress((void**)&q2,    g_q2);
    cudaGetSymbolAddress((void**)&bcat,  g_bcat);

    cudaFuncSetAttribute(hgemm<float>,  cudaFuncAttributeMaxDynamicSharedMemorySize, GSM_BYTES);
    cudaFuncSetAttribute(hgemm<__half>, cudaFuncAttributeMaxDynamicSharedMemorySize, GSM_BYTES);

    const int MN = Bsz * Nn;   // 16384

    // 0. operand preparation (single fused transpose launch + emb conversion)
    transpose_all<<<dim3(24, 16, 6), dim3(32, 8)>>>(W_in, W_out, W_ih, W_hh, fc1_w, fc2_w);
    embconv_kernel<<<(Vv * Hh / 4 + 255) / 256, 256>>>(emb);
    bcat_kernel<<<2, 256>>>(b_in, b_out);

    auto gemmF = [](const __half* X, const __half* W, const float* bias, float* C,
                    int M, int N, int K) {
        dim3 grid((N + 127) / 128, M / 128);
        hgemm<float><<<grid, 256, GSM_BYTES>>>(X, W, bias, C, M, N, K);
    };
    auto gemmH = [](const __half* X, const __half* W, const float* bias, __half* C,
                    int M, int N, int K) {
        dim3 grid((N + 127) / 128, M / 128);
        hgemm<__half><<<grid, 256, GSM_BYTES>>>(X, W, bias, C, M, N, K);
    };

    // 1. h = emb[items]
    embed_kernel<<<MN, Hh>>>(emb, items);
    // 2. tcat = h @ [W_in|W_out] + [b_in|b_out]   (half out)
    gemmH(hh, wcat, bcat, tcat, MN, 2 * Hh, Hh);
    // 3. a = [A_in@tin | A_out@tout]
    amsg_kernel<<<dim3(Bsz, 2, 2), 128>>>(A);
    // 4. gi = a@W_ih+b_ih ; gh = h@W_hh+b_hh
    gemmF(ah, wih, b_ih, gi, MN, 3 * Hh, 2 * Hh);
    gemmF(hh, whh, b_hh, gh, MN, 3 * Hh, Hh);
    // 5. GRU update
    gru_kernel<<<MN * Hh / 256, 256>>>();
    // 6. gather
    gather_kernel<<<Bsz, Hh>>>(alias, mask);
    // 7. q1, q2
    gemmF(htail, wf1, fc1_b, q1, Bsz, Hh, Hh);
    gemmF(hseqs, wf2, fc2_b, q2, Bsz * Ll, Hh, Hh);
    // 8. alpha ; seq_emb
    alpha_kernel<<<Bsz * Ll, Hh>>>(fc3_w);
    seqemb_kernel<<<Bsz, Hh>>>(mask);
    // 9. out = seq_emb @ emb[1:].T
    gemmF(semb, embh, nullptr, out, Bsz, Vv, Hh);
}